// round 16
// baseline (speedup 1.0000x reference)
#include <cuda_runtime.h>
#include <cuda_bf16.h>
#include <math.h>
#include <stdint.h>

#define BB 32
#define AA 100000
#define CC 81
#define NANCH (BB*AA)
#define CTAS_PER_SAMPLE 3125           /* 100000 / 32 anchors per CTA */

// Scratch (no cudaMalloc allowed) — static device globals (zero-initialized;
// every kernel sequence leaves them zeroed again -> graph-replay safe).
// g_work: positives tagged negative (-(ce+sl1)), negatives hold -logp0 (>0).
__device__ float    g_work[NANCH];
__device__ unsigned g_hist[BB * 2048];          // level-0 hist, built by k1
__device__ int      g_npg[BB];                  // positive count per sample
__device__ unsigned long long g_psg[BB];        // psum, fixed-point 2^26
__device__ float    g_sample[BB];
__device__ int      g_done;

// ---------------------------------------------------------------------------
// Packed f32x2 helpers (Blackwell FFMA2 path — only reachable via PTX)
// ---------------------------------------------------------------------------
__device__ __forceinline__ uint64_t pk(float lo, float hi) {
    uint64_t r; asm("mov.b64 %0, {%1, %2};" : "=l"(r) : "f"(lo), "f"(hi)); return r;
}
__device__ __forceinline__ uint64_t pk2(float c) { return pk(c, c); }
__device__ __forceinline__ void upk(uint64_t v, float& lo, float& hi) {
    asm("mov.b64 {%0, %1}, %2;" : "=f"(lo), "=f"(hi) : "l"(v));
}
__device__ __forceinline__ uint64_t f2fma(uint64_t a, uint64_t b, uint64_t c) {
    uint64_t d; asm("fma.rn.f32x2 %0, %1, %2, %3;" : "=l"(d) : "l"(a), "l"(b), "l"(c)); return d;
}
__device__ __forceinline__ uint64_t f2add(uint64_t a, uint64_t b) {
    uint64_t d; asm("add.rn.f32x2 %0, %1, %2;" : "=l"(d) : "l"(a), "l"(b)); return d;
}
__device__ __forceinline__ uint64_t f2mul(uint64_t a, uint64_t b) {
    uint64_t d; asm("mul.rn.f32x2 %0, %1, %2;" : "=l"(d) : "l"(a), "l"(b)); return d;
}

// Packed exp of two independent floats. FFMA-only + exponent injection.
// deg-4 poly of 2^f on [-0.5,0.5]: rel err ~6e-5 (R11-exact, measured-fast).
__device__ __forceinline__ uint64_t pexp(float xlo, float xhi) {
    uint64_t x  = pk(xlo, xhi);
    uint64_t y  = f2mul(x, pk2(1.4426950408889634f));
    uint64_t t  = f2add(y, pk2(12582912.0f));
    uint64_t nf = f2add(t, pk2(-12582912.0f));
    uint64_t f  = f2fma(nf, pk2(-1.0f), y);            // y - nf
    uint64_t p  = pk2(0.009618129107628477f);
    p = f2fma(p, f, pk2(0.05550410866482158f));
    p = f2fma(p, f, pk2(0.2402265069591007f));
    p = f2fma(p, f, pk2(0.6931471805599453f));
    p = f2fma(p, f, pk2(1.0f));
    float tlo, thi, plo, phi;
    upk(t, tlo, thi); upk(p, plo, phi);
    float rlo = __uint_as_float(__float_as_uint(plo) + ((unsigned)__float_as_int(tlo) << 23));
    float rhi = __uint_as_float(__float_as_uint(phi) + ((unsigned)__float_as_int(thi) << 23));
    return pk(rlo, rhi);
}

// Monotonic total-order key for float (ascending float -> ascending unsigned)
__device__ __forceinline__ unsigned fkey(float f) {
    unsigned u = __float_as_uint(f);
    unsigned m = ((unsigned)((int)u >> 31)) | 0x80000000u;
    return u ^ m;
}
__device__ __forceinline__ float fkey_inv(unsigned k) {
    unsigned u = (k & 0x80000000u) ? (k ^ 0x80000000u) : ~k;
    return __uint_as_float(u);
}

// ===========================================================================
// Kernel 1: warp per 4 anchors — R11-exact hot path (measured local optimum:
// 199.8us @ DRAM 68%; all four perturbations tried in R13-R15 regressed).
// NEW: epilogue on lane 0 also feeds the level-0 histogram + np/psum tallies
// directly from registers (REDG no-return atomics, hidden under the
// memory-bound mainloop) -> kernel k2a and its 12.8MB pass are DELETED.
// psum uses fixed-point int64 atomics (x 2^26): order-independent ->
// deterministic. Tallies are consumed AND re-zeroed by k2b (replay-safe).
// ===========================================================================
__global__ __launch_bounds__(256)
void k1_per_anchor(const float* __restrict__ lp, const float* __restrict__ cp,
                   const float* __restrict__ lt, const int*   __restrict__ ct)
{
    int warp = (blockIdx.x * 256 + threadIdx.x) >> 5;   // 0 .. NANCH/4-1 exactly
    int lane = threadIdx.x & 31;
    int a0   = warp * 4;
    const float* r0 = cp + (size_t)a0 * CC;
    const bool tail = lane < 17;

    // ---- pair (anchor0, anchor1): lane pairs same element across rows ----
    float f0lo = r0[lane],           f0hi = r0[CC + lane];
    float f1lo = r0[lane + 32],      f1hi = r0[CC + lane + 32];
    float f2lo = 0.f, f2hi = 0.f;
    if (tail) { f2lo = r0[lane + 64]; f2hi = r0[CC + lane + 64]; }
    uint64_t acc = pexp(f0lo, f0hi);
    acc = f2add(acc, pexp(f1lo, f1hi));
    if (tail) acc = f2add(acc, pexp(f2lo, f2hi));

    // ---- pair (anchor2, anchor3) ----
    const float* r2p = r0 + 2 * CC;
    float g0lo = r2p[lane],          g0hi = r2p[CC + lane];
    float g1lo = r2p[lane + 32],     g1hi = r2p[CC + lane + 32];
    float g2lo = 0.f, g2hi = 0.f;
    if (tail) { g2lo = r2p[lane + 64]; g2hi = r2p[CC + lane + 64]; }
    uint64_t acc2 = pexp(g0lo, g0hi);
    acc2 = f2add(acc2, pexp(g1lo, g1hi));
    if (tail) acc2 = f2add(acc2, pexp(g2lo, g2hi));

    // Packed warp butterfly: both anchor-sums of a pair reduced together.
    #pragma unroll
    for (int o = 16; o; o >>= 1) {
        acc  = f2add(acc,  (uint64_t)__shfl_xor_sync(0xFFFFFFFFu, (unsigned long long)acc,  o));
        acc2 = f2add(acc2, (uint64_t)__shfl_xor_sync(0xFFFFFFFFu, (unsigned long long)acc2, o));
    }
    float s0, s1, s2, s3;
    upk(acc, s0, s1); upk(acc2, s2, s3);

    // __logf: MUFU.LG2 — only 1 per anchor (3.2M total), fully hidden.
    float lse0 = __logf(s0), lse1 = __logf(s1);
    float lse2 = __logf(s2), lse3 = __logf(s3);

    int4 tt = *(const int4*)(ct + a0);   // a0 % 4 == 0 -> 16B aligned

    auto handle = [&](int t, float lse, float v0, float v1, float v2,
                      int aidx) -> float {
        if (t != 0) {                                 // warp-uniform branch
            int sl = t >> 5, ln = t & 31;
            float vsl = (sl == 0) ? v0 : (sl == 1) ? v1 : v2;
            float xt = __shfl_sync(0xFFFFFFFFu, vsl, ln);
            float ce = lse - xt;
            float sl1 = 0.f;
            if (lane < 4) {
                size_t i4 = (size_t)aidx * 4 + lane;
                float d  = lp[i4] - lt[i4];
                float ad = fabsf(d);
                sl1 = (ad < 1.0f) ? 0.5f * d * d : ad - 0.5f;
            }
            sl1 += __shfl_xor_sync(0xFFFFFFFFu, sl1, 1);
            sl1 += __shfl_xor_sync(0xFFFFFFFFu, sl1, 2);
            sl1  = __shfl_sync(0xFFFFFFFFu, sl1, 0);
            return -(ce + sl1);                       // tag positive anchor: < 0
        }
        return lse - v0;                              // valid on lane 0 (writer)
    };

    float o0 = handle(tt.x, lse0, f0lo, f1lo, f2lo, a0);
    float o1 = handle(tt.y, lse1, f0hi, f1hi, f2hi, a0 + 1);
    float o2 = handle(tt.z, lse2, g0lo, g1lo, g2lo, a0 + 2);
    float o3 = handle(tt.w, lse3, g0hi, g1hi, g2hi, a0 + 3);
    if (lane == 0) {
        *(float4*)(g_work + a0) = make_float4(o0, o1, o2, o3);

        // ---- fused level-0 histogram + np/psum tallies (was kernel k2a) ----
        int b = blockIdx.x / CTAS_PER_SAMPLE;         // CTA fully inside one sample
        unsigned* h = g_hist + b * 2048;
        int np = 0; float ps = 0.f;
        float oo0 = o0, oo1 = o1, oo2 = o2, oo3 = o3;
        #pragma unroll
        for (int j = 0; j < 4; j++) {
            float o = (j == 0) ? oo0 : (j == 1) ? oo1 : (j == 2) ? oo2 : oo3;
            if (o < 0.f) { np++; ps -= o; }
            else atomicAdd(&h[fkey(o) >> 21], 1u);    // REDG, no-return
        }
        if (np) {
            atomicAdd(&g_npg[b], np);
            atomicAdd(&g_psg[b], (unsigned long long)(long long)(ps * 67108864.0f));
        }
    }
}

// ===========================================================================
// Kernel 2b: one CTA per sample. Radix-select levels 1-2 + top-k sum.
// (verbatim R11 3-pass structure — the measured-fast configuration)
// Consumes AND re-zeroes g_hist/g_npg/g_psg (graph-replay safe).
// Last finishing block produces the final scalar and resets g_done.
// ===========================================================================
__global__ __launch_bounds__(1024)
void k2b(float* __restrict__ out)
{
    const int b   = blockIdx.x;
    const int tid = threadIdx.x;
    const int NT  = 1024;
    const float4* w4 = (const float4*)(g_work + (size_t)b * AA);

    __shared__ unsigned hist[2048];
    __shared__ unsigned gpart[32];
    __shared__ float  s_f[32];
    __shared__ float  sh_psum;
    __shared__ int    sh_np, sh_k;
    __shared__ int    sh_b0, sh_r0, sh_b1, sh_r1, sh_b2, sh_r2;

    for (int i = tid; i < 2048; i += NT) {            // load + self-clean
        hist[i] = g_hist[b * 2048 + i];
        g_hist[b * 2048 + i] = 0;
    }
    if (tid == 0) {
        int N = g_npg[b];                 g_npg[b] = 0;
        unsigned long long P = g_psg[b];  g_psg[b] = 0ull;
        sh_psum = (float)(long long)P * (1.0f / 67108864.0f);
        sh_np = N;
        int k = 3 * N; int avail = AA - N;
        if (k > avail) k = avail;
        sh_k = k;
    }
    __syncthreads();
    const int k = sh_k;

    auto select_bucket = [&](int r_in, int* out_b, int* out_r) {
        if (tid < 32) {
            unsigned s = 0;
            #pragma unroll 8
            for (int j = 0; j < 64; j++) s += hist[tid * 64 + j];
            gpart[tid] = s;
        }
        __syncthreads();
        if (tid == 0) {
            if (r_in <= 0) { *out_b = 0; *out_r = 0; }
            else {
                unsigned cum = 0; int g = 31;
                for (; g > 0; g--) {
                    if (cum + gpart[g] >= (unsigned)r_in) break;
                    cum += gpart[g];
                }
                int bb = g * 64;
                for (int j = 63; j >= 0; j--) {
                    unsigned c = hist[g * 64 + j];
                    if (cum + c >= (unsigned)r_in) { bb = g * 64 + j; break; }
                    cum += c;
                }
                *out_b = bb; *out_r = r_in - (int)cum;
            }
        }
        __syncthreads();
    };

    select_bucket(k, &sh_b0, &sh_r0);
    const unsigned b0 = (unsigned)sh_b0;
    const int r0 = sh_r0;

    // ---- Level 1: bits [20:10] within bucket b0 ----
    for (int i = tid; i < 2048; i += NT) hist[i] = 0;
    __syncthreads();
    #pragma unroll 2
    for (int i = tid; i < AA / 4; i += NT) {
        float4 q = w4[i];
        #pragma unroll
        for (int c = 0; c < 4; c++) {
            float v = (c == 0) ? q.x : (c == 1) ? q.y : (c == 2) ? q.z : q.w;
            if (v < 0.f) continue;
            unsigned kb = fkey(v);
            if ((kb >> 21) == b0) atomicAdd(&hist[(kb >> 10) & 2047u], 1u);
        }
    }
    __syncthreads();
    select_bucket(r0, &sh_b1, &sh_r1);
    const unsigned prefix = (b0 << 11) | (unsigned)sh_b1;
    const int r1 = sh_r1;

    // ---- Level 2: bits [9:0] within prefix ----
    for (int i = tid; i < 2048; i += NT) hist[i] = 0;
    __syncthreads();
    #pragma unroll 2
    for (int i = tid; i < AA / 4; i += NT) {
        float4 q = w4[i];
        #pragma unroll
        for (int c = 0; c < 4; c++) {
            float v = (c == 0) ? q.x : (c == 1) ? q.y : (c == 2) ? q.z : q.w;
            if (v < 0.f) continue;
            unsigned kb = fkey(v);
            if ((kb >> 10) == prefix) atomicAdd(&hist[kb & 1023u], 1u);
        }
    }
    __syncthreads();
    select_bucket(r1, &sh_b2, &sh_r2);
    const unsigned T  = (prefix << 10) | (unsigned)sh_b2;  // exact threshold key
    const int r2 = sh_r2;                                   // # taken at == T

    // ---- Sum of values strictly greater than threshold ----
    float s = 0.f;
    #pragma unroll 2
    for (int i = tid; i < AA / 4; i += NT) {
        float4 q = w4[i];
        #pragma unroll
        for (int c = 0; c < 4; c++) {
            float v = (c == 0) ? q.x : (c == 1) ? q.y : (c == 2) ? q.z : q.w;
            if (v < 0.f) continue;
            if (fkey(v) > T) s += v;
        }
    }
    #pragma unroll
    for (int o = 16; o; o >>= 1) s += __shfl_xor_sync(0xFFFFFFFFu, s, o);
    if ((tid & 31) == 0) s_f[tid >> 5] = s;
    __syncthreads();
    if (tid == 0) {
        float S = 0.f;
        for (int w = 0; w < 32; w++) S += s_f[w];
        int npT = sh_np;
        float loss = 0.f;
        if (npT > 0) {
            float neg_sum = S + (float)r2 * fkey_inv(T);   // ties at threshold
            loss = (sh_psum + neg_sum) / (float)npT;
        }
        g_sample[b] = loss;
        __threadfence();
        int prev = atomicAdd(&g_done, 1);
        if (prev == BB - 1) {                     // last block: fused final sum
            float tot = 0.f;
            for (int i = 0; i < BB; i++) tot += g_sample[i];
            out[0] = tot;
            g_done = 0;                           // self-clean for next replay
        }
    }
}

extern "C" void kernel_launch(void* const* d_in, const int* in_sizes, int n_in,
                              void* d_out, int out_size)
{
    const float* lp = nullptr; const float* cp = nullptr;
    const float* lt = nullptr; const int*   ct = nullptr;
    int locIdx[2] = {-1, -1}; int nl = 0;
    for (int i = 0; i < n_in; i++) {
        if (in_sizes[i] == BB * AA * CC)      cp = (const float*)d_in[i];
        else if (in_sizes[i] == BB * AA)      ct = (const int*)d_in[i];
        else if (in_sizes[i] == BB * AA * 4) { if (nl < 2) locIdx[nl] = i; nl++; }
    }
    lp = (const float*)d_in[locIdx[0]];
    lt = (const float*)d_in[locIdx[1]];

    k1_per_anchor<<<NANCH / 32, 256>>>(lp, cp, lt, ct); // warp per 4 anchors
    k2b<<<BB, 1024>>>((float*)d_out);
}

// round 17
// speedup vs baseline: 7.0044x; 7.0044x over previous
#include <cuda_runtime.h>
#include <cuda_bf16.h>
#include <math.h>
#include <stdint.h>

#define BB 32
#define AA 100000
#define CC 81
#define NANCH (BB*AA)
#define NCHUNK 25
#define CHUNK_ELEM (AA / NCHUNK)      /* 4000 */
#define CHUNK_V4   (CHUNK_ELEM / 4)   /* 1000 */

// Scratch (no cudaMalloc allowed) — static device globals.
// g_work: positives tagged negative (-(ce+sl1)), negatives hold -logp0 (>0).
__device__ float    g_work[NANCH];
__device__ unsigned g_hist[BB * 2048];
__device__ float    g_psum_part[BB * NCHUNK];
__device__ int      g_np_part[BB * NCHUNK];
__device__ float    g_sample[BB];
__device__ int      g_done;

// ---------------------------------------------------------------------------
// Packed f32x2 helpers (Blackwell FFMA2 path — only reachable via PTX)
// ---------------------------------------------------------------------------
__device__ __forceinline__ uint64_t pk(float lo, float hi) {
    uint64_t r; asm("mov.b64 %0, {%1, %2};" : "=l"(r) : "f"(lo), "f"(hi)); return r;
}
__device__ __forceinline__ uint64_t pk2(float c) { return pk(c, c); }
__device__ __forceinline__ void upk(uint64_t v, float& lo, float& hi) {
    asm("mov.b64 {%0, %1}, %2;" : "=f"(lo), "=f"(hi) : "l"(v));
}
__device__ __forceinline__ uint64_t f2fma(uint64_t a, uint64_t b, uint64_t c) {
    uint64_t d; asm("fma.rn.f32x2 %0, %1, %2, %3;" : "=l"(d) : "l"(a), "l"(b), "l"(c)); return d;
}
__device__ __forceinline__ uint64_t f2add(uint64_t a, uint64_t b) {
    uint64_t d; asm("add.rn.f32x2 %0, %1, %2;" : "=l"(d) : "l"(a), "l"(b)); return d;
}
__device__ __forceinline__ uint64_t f2mul(uint64_t a, uint64_t b) {
    uint64_t d; asm("mul.rn.f32x2 %0, %1, %2;" : "=l"(d) : "l"(a), "l"(b)); return d;
}

// Packed exp of two independent floats. FFMA-only + exponent injection.
// deg-4 poly of 2^f on [-0.5,0.5]: rel err ~6e-5 (budget 1e-3 -> huge margin).
__device__ __forceinline__ uint64_t pexp(float xlo, float xhi) {
    uint64_t x  = pk(xlo, xhi);
    uint64_t y  = f2mul(x, pk2(1.4426950408889634f));
    uint64_t t  = f2add(y, pk2(12582912.0f));
    uint64_t nf = f2add(t, pk2(-12582912.0f));
    uint64_t f  = f2fma(nf, pk2(-1.0f), y);            // y - nf
    uint64_t p  = pk2(0.009618129107628477f);
    p = f2fma(p, f, pk2(0.05550410866482158f));
    p = f2fma(p, f, pk2(0.2402265069591007f));
    p = f2fma(p, f, pk2(0.6931471805599453f));
    p = f2fma(p, f, pk2(1.0f));
    float tlo, thi, plo, phi;
    upk(t, tlo, thi); upk(p, plo, phi);
    float rlo = __uint_as_float(__float_as_uint(plo) + ((unsigned)__float_as_int(tlo) << 23));
    float rhi = __uint_as_float(__float_as_uint(phi) + ((unsigned)__float_as_int(thi) << 23));
    return pk(rlo, rhi);
}

// Monotonic total-order key for float (ascending float -> ascending unsigned)
__device__ __forceinline__ unsigned fkey(float f) {
    unsigned u = __float_as_uint(f);
    unsigned m = ((unsigned)((int)u >> 31)) | 0x80000000u;
    return u ^ m;
}
__device__ __forceinline__ float fkey_inv(unsigned k) {
    unsigned u = (k & 0x80000000u) ? (k ^ 0x80000000u) : ~k;
    return __uint_as_float(u);
}

// ===========================================================================
// Kernel 1: warp per 4 anchors. Packed-pair (anchor j, anchor j+1) exp.
// (R11 bit-exact — measured local optimum: 199.8us @ DRAM 68%. All four
// perturbations in R13-R16 regressed; do not touch.)
// ===========================================================================
__global__ __launch_bounds__(256)
void k1_per_anchor(const float* __restrict__ lp, const float* __restrict__ cp,
                   const float* __restrict__ lt, const int*   __restrict__ ct)
{
    // Fold g_hist zeroing into the first 64 blocks (kernel boundary orders
    // this before k2a's atomics).
    if (blockIdx.x < 64) {
        int zb = blockIdx.x * 1024;
        for (int i = threadIdx.x; i < 1024; i += 256) g_hist[zb + i] = 0;
    }

    int warp = (blockIdx.x * 256 + threadIdx.x) >> 5;   // 0 .. NANCH/4-1 exactly
    int lane = threadIdx.x & 31;
    int a0   = warp * 4;
    const float* r0 = cp + (size_t)a0 * CC;
    const bool tail = lane < 17;

    // ---- pair (anchor0, anchor1): lane pairs same element across rows ----
    float f0lo = r0[lane],           f0hi = r0[CC + lane];
    float f1lo = r0[lane + 32],      f1hi = r0[CC + lane + 32];
    float f2lo = 0.f, f2hi = 0.f;
    if (tail) { f2lo = r0[lane + 64]; f2hi = r0[CC + lane + 64]; }
    uint64_t acc = pexp(f0lo, f0hi);
    acc = f2add(acc, pexp(f1lo, f1hi));
    if (tail) acc = f2add(acc, pexp(f2lo, f2hi));

    // ---- pair (anchor2, anchor3) ----
    const float* r2p = r0 + 2 * CC;
    float g0lo = r2p[lane],          g0hi = r2p[CC + lane];
    float g1lo = r2p[lane + 32],     g1hi = r2p[CC + lane + 32];
    float g2lo = 0.f, g2hi = 0.f;
    if (tail) { g2lo = r2p[lane + 64]; g2hi = r2p[CC + lane + 64]; }
    uint64_t acc2 = pexp(g0lo, g0hi);
    acc2 = f2add(acc2, pexp(g1lo, g1hi));
    if (tail) acc2 = f2add(acc2, pexp(g2lo, g2hi));

    // Packed warp butterfly: both anchor-sums of a pair reduced together.
    #pragma unroll
    for (int o = 16; o; o >>= 1) {
        acc  = f2add(acc,  (uint64_t)__shfl_xor_sync(0xFFFFFFFFu, (unsigned long long)acc,  o));
        acc2 = f2add(acc2, (uint64_t)__shfl_xor_sync(0xFFFFFFFFu, (unsigned long long)acc2, o));
    }
    float s0, s1, s2, s3;
    upk(acc, s0, s1); upk(acc2, s2, s3);

    // __logf: MUFU.LG2 — only 1 per anchor (3.2M total), fully hidden.
    float lse0 = __logf(s0), lse1 = __logf(s1);
    float lse2 = __logf(s2), lse3 = __logf(s3);

    int4 tt = *(const int4*)(ct + a0);   // a0 % 4 == 0 -> 16B aligned

    auto handle = [&](int t, float lse, float v0, float v1, float v2,
                      int aidx) -> float {
        if (t != 0) {                                 // warp-uniform branch
            int sl = t >> 5, ln = t & 31;
            float vsl = (sl == 0) ? v0 : (sl == 1) ? v1 : v2;
            float xt = __shfl_sync(0xFFFFFFFFu, vsl, ln);
            float ce = lse - xt;
            float sl1 = 0.f;
            if (lane < 4) {
                size_t i4 = (size_t)aidx * 4 + lane;
                float d  = lp[i4] - lt[i4];
                float ad = fabsf(d);
                sl1 = (ad < 1.0f) ? 0.5f * d * d : ad - 0.5f;
            }
            sl1 += __shfl_xor_sync(0xFFFFFFFFu, sl1, 1);
            sl1 += __shfl_xor_sync(0xFFFFFFFFu, sl1, 2);
            sl1  = __shfl_sync(0xFFFFFFFFu, sl1, 0);
            return -(ce + sl1);                       // tag positive anchor: < 0
        }
        return lse - v0;                              // valid on lane 0 (writer)
    };

    float o0 = handle(tt.x, lse0, f0lo, f1lo, f2lo, a0);
    float o1 = handle(tt.y, lse1, f0hi, f1hi, f2hi, a0 + 1);
    float o2 = handle(tt.z, lse2, g0lo, g1lo, g2lo, a0 + 2);
    float o3 = handle(tt.w, lse3, g0hi, g1hi, g2hi, a0 + 3);
    if (lane == 0)
        *(float4*)(g_work + a0) = make_float4(o0, o1, o2, o3);
}

// ===========================================================================
// Kernel 2a: 800 CTAs (25 chunks/sample; was 8). Level-0 histogram + psum/np
// partials. Same code path as the measured-fast R11 version — only the
// chunking constant changed, to raise chip-wide MLP on this L2-latency-bound
// scan and smooth the wave structure (800 vs 256 CTAs on 148 SMs).
// ===========================================================================
__global__ __launch_bounds__(256)
void k2a()
{
    if (blockIdx.x == 0 && threadIdx.x == 0) g_done = 0;  // ordered by kernel boundary

    const int b = blockIdx.x / NCHUNK, chunk = blockIdx.x % NCHUNK;
    const float4* w4 = (const float4*)(g_work + (size_t)b * AA) + chunk * CHUNK_V4;
    __shared__ unsigned hist[2048];
    __shared__ float sf[8];
    __shared__ int   si[8];
    for (int i = threadIdx.x; i < 2048; i += 256) hist[i] = 0;
    __syncthreads();

    float psum = 0.f; int np = 0;
    for (int i = threadIdx.x; i < CHUNK_V4; i += 256) {
        float4 q = w4[i];
        float vv0 = q.x, vv1 = q.y, vv2 = q.z, vv3 = q.w;
        #pragma unroll
        for (int c = 0; c < 4; c++) {
            float v = (c == 0) ? vv0 : (c == 1) ? vv1 : (c == 2) ? vv2 : vv3;
            if (v < 0.f) { np++; psum -= v; }
            else atomicAdd(&hist[fkey(v) >> 21], 1u);
        }
    }
    __syncthreads();
    for (int i = threadIdx.x; i < 2048; i += 256) {
        unsigned c = hist[i];
        if (c) atomicAdd(&g_hist[b * 2048 + i], c);
    }
    #pragma unroll
    for (int o = 16; o; o >>= 1) {
        psum += __shfl_xor_sync(0xFFFFFFFFu, psum, o);
        np   += __shfl_xor_sync(0xFFFFFFFFu, np, o);
    }
    if ((threadIdx.x & 31) == 0) { sf[threadIdx.x >> 5] = psum; si[threadIdx.x >> 5] = np; }
    __syncthreads();
    if (threadIdx.x == 0) {
        float P = 0.f; int N = 0;
        for (int w = 0; w < 8; w++) { P += sf[w]; N += si[w]; }
        g_psum_part[blockIdx.x] = P;
        g_np_part[blockIdx.x]   = N;
    }
}

// ===========================================================================
// Kernel 2b: one CTA per sample. Radix-select levels 1-2 + top-k sum.
// (verbatim R11 3-pass structure — the measured-fast configuration)
// Last finishing block also produces the final scalar.
// ===========================================================================
__global__ __launch_bounds__(1024)
void k2b(float* __restrict__ out)
{
    const int b   = blockIdx.x;
    const int tid = threadIdx.x;
    const int NT  = 1024;
    const float4* w4 = (const float4*)(g_work + (size_t)b * AA);

    __shared__ unsigned hist[2048];
    __shared__ unsigned gpart[32];
    __shared__ float  s_f[32];
    __shared__ float  sh_psum;
    __shared__ int    sh_np, sh_k;
    __shared__ int    sh_b0, sh_r0, sh_b1, sh_r1, sh_b2, sh_r2;

    for (int i = tid; i < 2048; i += NT) hist[i] = g_hist[b * 2048 + i];
    if (tid == 0) {
        float P = 0.f; int N = 0;
        for (int j = 0; j < NCHUNK; j++) {
            P += g_psum_part[b * NCHUNK + j];
            N += g_np_part[b * NCHUNK + j];
        }
        sh_psum = P; sh_np = N;
        int k = 3 * N; int avail = AA - N;
        if (k > avail) k = avail;
        sh_k = k;
    }
    __syncthreads();
    const int k = sh_k;

    auto select_bucket = [&](int r_in, int* out_b, int* out_r) {
        if (tid < 32) {
            unsigned s = 0;
            #pragma unroll 8
            for (int j = 0; j < 64; j++) s += hist[tid * 64 + j];
            gpart[tid] = s;
        }
        __syncthreads();
        if (tid == 0) {
            if (r_in <= 0) { *out_b = 0; *out_r = 0; }
            else {
                unsigned cum = 0; int g = 31;
                for (; g > 0; g--) {
                    if (cum + gpart[g] >= (unsigned)r_in) break;
                    cum += gpart[g];
                }
                int bb = g * 64;
                for (int j = 63; j >= 0; j--) {
                    unsigned c = hist[g * 64 + j];
                    if (cum + c >= (unsigned)r_in) { bb = g * 64 + j; break; }
                    cum += c;
                }
                *out_b = bb; *out_r = r_in - (int)cum;
            }
        }
        __syncthreads();
    };

    select_bucket(k, &sh_b0, &sh_r0);
    const unsigned b0 = (unsigned)sh_b0;
    const int r0 = sh_r0;

    // ---- Level 1: bits [20:10] within bucket b0 ----
    for (int i = tid; i < 2048; i += NT) hist[i] = 0;
    __syncthreads();
    #pragma unroll 2
    for (int i = tid; i < AA / 4; i += NT) {
        float4 q = w4[i];
        #pragma unroll
        for (int c = 0; c < 4; c++) {
            float v = (c == 0) ? q.x : (c == 1) ? q.y : (c == 2) ? q.z : q.w;
            if (v < 0.f) continue;
            unsigned kb = fkey(v);
            if ((kb >> 21) == b0) atomicAdd(&hist[(kb >> 10) & 2047u], 1u);
        }
    }
    __syncthreads();
    select_bucket(r0, &sh_b1, &sh_r1);
    const unsigned prefix = (b0 << 11) | (unsigned)sh_b1;
    const int r1 = sh_r1;

    // ---- Level 2: bits [9:0] within prefix ----
    for (int i = tid; i < 2048; i += NT) hist[i] = 0;
    __syncthreads();
    #pragma unroll 2
    for (int i = tid; i < AA / 4; i += NT) {
        float4 q = w4[i];
        #pragma unroll
        for (int c = 0; c < 4; c++) {
            float v = (c == 0) ? q.x : (c == 1) ? q.y : (c == 2) ? q.z : q.w;
            if (v < 0.f) continue;
            unsigned kb = fkey(v);
            if ((kb >> 10) == prefix) atomicAdd(&hist[kb & 1023u], 1u);
        }
    }
    __syncthreads();
    select_bucket(r1, &sh_b2, &sh_r2);
    const unsigned T  = (prefix << 10) | (unsigned)sh_b2;  // exact threshold key
    const int r2 = sh_r2;                                   // # taken at == T

    // ---- Sum of values strictly greater than threshold ----
    float s = 0.f;
    #pragma unroll 2
    for (int i = tid; i < AA / 4; i += NT) {
        float4 q = w4[i];
        #pragma unroll
        for (int c = 0; c < 4; c++) {
            float v = (c == 0) ? q.x : (c == 1) ? q.y : (c == 2) ? q.z : q.w;
            if (v < 0.f) continue;
            if (fkey(v) > T) s += v;
        }
    }
    #pragma unroll
    for (int o = 16; o; o >>= 1) s += __shfl_xor_sync(0xFFFFFFFFu, s, o);
    if ((tid & 31) == 0) s_f[tid >> 5] = s;
    __syncthreads();
    if (tid == 0) {
        float S = 0.f;
        for (int w = 0; w < 32; w++) S += s_f[w];
        int npT = sh_np;
        float loss = 0.f;
        if (npT > 0) {
            float neg_sum = S + (float)r2 * fkey_inv(T);   // ties at threshold
            loss = (sh_psum + neg_sum) / (float)npT;
        }
        g_sample[b] = loss;
        __threadfence();
        int prev = atomicAdd(&g_done, 1);
        if (prev == BB - 1) {                     // last block: fused final sum
            float tot = 0.f;
            for (int i = 0; i < BB; i++) tot += g_sample[i];
            out[0] = tot;
        }
    }
}

extern "C" void kernel_launch(void* const* d_in, const int* in_sizes, int n_in,
                              void* d_out, int out_size)
{
    const float* lp = nullptr; const float* cp = nullptr;
    const float* lt = nullptr; const int*   ct = nullptr;
    int locIdx[2] = {-1, -1}; int nl = 0;
    for (int i = 0; i < n_in; i++) {
        if (in_sizes[i] == BB * AA * CC)      cp = (const float*)d_in[i];
        else if (in_sizes[i] == BB * AA)      ct = (const int*)d_in[i];
        else if (in_sizes[i] == BB * AA * 4) { if (nl < 2) locIdx[nl] = i; nl++; }
    }
    lp = (const float*)d_in[locIdx[0]];
    lt = (const float*)d_in[locIdx[1]];

    k1_per_anchor<<<NANCH / 32, 256>>>(lp, cp, lt, ct); // warp per 4 anchors
    k2a<<<BB * NCHUNK, 256>>>();
    k2b<<<BB, 1024>>>((float*)d_out);
}